// round 1
// baseline (speedup 1.0000x reference)
#include <cuda_runtime.h>
#include <cstdint>
#include <cstdio>

#define TT 8
#define BB 8
#define CINC 128
#define HID 64
#define GG 256      // 4*HID gate channels
#define HWSZ 1024   // 32*32
#define OUTC 64

// ---------------- scratch (device globals; no allocations allowed) ----------
__device__ float g_gates[(size_t)2 * TT * BB * GG * HWSZ];   // [dir][t][b][256][1024] (134MB)
__device__ float g_xs1[(size_t)TT * BB * 2 * HID * HWSZ];    // layer-1 input  [t][b][128][1024]
__device__ float g_h[(size_t)2 * BB * HID * HWSZ];           // [dir][b][64][1024]
__device__ float g_c[(size_t)2 * BB * HID * HWSZ];
__device__ float g_last[(size_t)BB * 2 * HID * HWSZ];        // concat(hf1[-1], hr1[-1])

// ---------------- packed f32x2 helpers --------------------------------------
__device__ __forceinline__ unsigned long long pack2(float lo, float hi) {
    unsigned long long r;
    asm("mov.b64 %0, {%1, %2};" : "=l"(r) : "f"(lo), "f"(hi));
    return r;
}
__device__ __forceinline__ void unpack2(unsigned long long v, float& lo, float& hi) {
    asm("mov.b64 {%0, %1}, %2;" : "=f"(lo), "=f"(hi) : "l"(v));
}
__device__ __forceinline__ unsigned long long fma2(unsigned long long a,
                                                   unsigned long long b,
                                                   unsigned long long c) {
    unsigned long long d;
    asm("fma.rn.f32x2 %0, %1, %2, %3;" : "=l"(d) : "l"(a), "l"(b), "l"(c));
    return d;
}

// ---------------- 3x3 SAME conv, 32x32 images -------------------------------
// Tile: 32 wide x 16 tall, 128 threads (each thread: column x, 4 consecutive rows).
// OC block: 32 of 256 gate channels. Cin chunked by 8 through smem.
// MODE 0: layer-0 ih conv from `features` ([B][T][C][H][W]), both dirs in grid.z,
//         writes gates = conv + b_ih + b_hh.
// MODE 1: hh step conv, accumulates into gates[dir][t_eff][b]; dirs in grid.z.
// MODE 2: generic contiguous image list ([z][Cin][H][W]) -> gates[z], writes + biases.
constexpr int TW = 32, TH = 16, CK = 8, OCB = 32;

template <int CIN_T, int MODE>
__global__ void __launch_bounds__(128)
conv3x3_kernel(const float* __restrict__ in_base,
               const float* __restrict__ w0, const float* __restrict__ w1,
               const float* __restrict__ bih0, const float* __restrict__ bhh0,
               const float* __restrict__ bih1, const float* __restrict__ bhh1,
               float* __restrict__ out_base, int t)
{
    __shared__ float s_in[CK * 18 * 34];                    // 19.6 KB
    __shared__ __align__(16) float s_w[OCB * CK * 9 * 2];   // duplicated pairs, 18.4 KB

    const int tid = threadIdx.x;
    const int x   = tid & 31;
    const int ys4 = (tid >> 5) << 2;           // 0,4,8,12
    const int y0  = blockIdx.x * TH;           // 0 or 16
    const int oc0 = blockIdx.y * OCB;
    const int z   = blockIdx.z;

    const float* in_img;
    const float* w;
    const float* bih = bih0;
    const float* bhh = bhh0;
    float* out_img;

    if (MODE == 0) {
        int dir = z >> 6;
        int tt  = (z >> 3) & 7;
        int b   = z & 7;
        in_img  = in_base + (size_t)(b * TT + tt) * CIN_T * HWSZ;
        w       = dir ? w1 : w0;
        bih     = dir ? bih1 : bih0;
        bhh     = dir ? bhh1 : bhh0;
        out_img = out_base + (size_t)z * GG * HWSZ;
    } else if (MODE == 1) {
        int dir = z >> 3;
        int b   = z & 7;
        in_img  = in_base + (size_t)z * CIN_T * HWSZ;
        w       = dir ? w1 : w0;
        int teff = dir ? (TT - 1 - t) : t;
        out_img = out_base + (size_t)((dir * TT + teff) * BB + b) * GG * HWSZ;
    } else {
        in_img  = in_base + (size_t)z * CIN_T * HWSZ;
        w       = w0;
        out_img = out_base + (size_t)z * GG * HWSZ;
    }

    unsigned long long acc01[OCB], acc23[OCB];
#pragma unroll
    for (int oc = 0; oc < OCB; oc++) { acc01[oc] = 0ULL; acc23[oc] = 0ULL; }

    for (int cb = 0; cb < CIN_T; cb += CK) {
        __syncthreads();
        // ---- load input chunk with halo (zero-padded) ----
        const float* inp = in_img + (size_t)cb * HWSZ;
        for (int i = tid; i < CK * 18 * 34; i += 128) {
            int ci = i / (18 * 34);
            int r  = i - ci * (18 * 34);
            int yy = r / 34;
            int xx = r - yy * 34;
            int gy = y0 + yy - 1;
            int gx = xx - 1;
            float v = 0.f;
            if ((unsigned)gy < 32u && (unsigned)gx < 32u)
                v = inp[ci * HWSZ + gy * 32 + gx];
            s_in[i] = v;
        }
        // ---- load weights, duplicated into f32x2 pairs ----
        for (int i = tid; i < OCB * CK * 9; i += 128) {
            int oc = i / (CK * 9);
            int r  = i - oc * (CK * 9);   // r = ci*9 + k
            float wv = w[(size_t)(oc0 + oc) * CIN_T * 9 + (size_t)cb * 9 + r];
            s_w[(oc * (CK * 9) + r) * 2 + 0] = wv;
            s_w[(oc * (CK * 9) + r) * 2 + 1] = wv;
        }
        __syncthreads();

        // ---- compute ----
        for (int ci = 0; ci < CK; ci++) {
#pragma unroll
            for (int ky = 0; ky < 3; ky++) {
                const float* ib = s_in + ci * (18 * 34) + (ys4 + ky) * 34 + x;
                const unsigned long long* wb =
                    reinterpret_cast<const unsigned long long*>(s_w) + ci * 9 + ky * 3;
#pragma unroll
                for (int kx = 0; kx < 3; kx++) {
                    float i0 = ib[kx];
                    float i1 = ib[kx + 34];
                    float i2 = ib[kx + 68];
                    float i3 = ib[kx + 102];
                    unsigned long long p01 = pack2(i0, i1);
                    unsigned long long p23 = pack2(i2, i3);
#pragma unroll
                    for (int oc = 0; oc < OCB; oc++) {
                        unsigned long long wv = wb[oc * (CK * 9) + kx];
                        acc01[oc] = fma2(wv, p01, acc01[oc]);
                        acc23[oc] = fma2(wv, p23, acc23[oc]);
                    }
                }
            }
        }
    }

    // ---- epilogue ----
#pragma unroll 4
    for (int oc = 0; oc < OCB; oc++) {
        float a0, a1, a2, a3;
        unpack2(acc01[oc], a0, a1);
        unpack2(acc23[oc], a2, a3);
        float* op = out_img + (size_t)(oc0 + oc) * HWSZ + (y0 + ys4) * 32 + x;
        if (MODE == 1) {
            op[0]  += a0; op[32] += a1; op[64] += a2; op[96] += a3;
        } else {
            float bv = bih[oc0 + oc] + bhh[oc0 + oc];
            op[0]  = a0 + bv; op[32] = a1 + bv; op[64] = a2 + bv; op[96] = a3 + bv;
        }
    }
}

// ---------------- pointwise LSTM cell update --------------------------------
__device__ __forceinline__ float sigmoidf_(float v) { return 1.f / (1.f + expf(-v)); }

__global__ void cell_kernel(const float* __restrict__ gates,
                            float* __restrict__ h, float* __restrict__ c,
                            float* __restrict__ xs1, float* __restrict__ last,
                            int t, int zero_init, int last_choff, int ndir)
{
    int idx = blockIdx.x * blockDim.x + threadIdx.x;
    if (idx >= ndir * BB * HID * HWSZ) return;
    int px = idx & (HWSZ - 1);
    int r  = idx >> 10;
    int hc = r & (HID - 1);
    r >>= 6;
    int b   = r & 7;
    int dir = r >> 3;
    int teff = dir ? (TT - 1 - t) : t;

    size_t gb = ((size_t)((dir * TT + teff) * BB + b) * GG) * HWSZ + px;
    float gi = gates[gb + (size_t)hc * HWSZ];
    float gf = gates[gb + (size_t)(hc + HID) * HWSZ];
    float gg = gates[gb + (size_t)(hc + 2 * HID) * HWSZ];
    float go = gates[gb + (size_t)(hc + 3 * HID) * HWSZ];

    float cp = zero_init ? 0.f : c[idx];
    float cn = sigmoidf_(gf) * cp + sigmoidf_(gi) * tanhf(gg);
    float hn = sigmoidf_(go) * tanhf(cn);
    c[idx] = cn;
    h[idx] = hn;
    if (xs1)
        xs1[(((size_t)teff * BB + b) * (2 * HID) + dir * HID + hc) * HWSZ + px] = hn;
    if (last)
        last[((size_t)b * (2 * HID) + last_choff + hc) * HWSZ + px] = hn;
}

// ---------------- 1x1 conv + ReLU head --------------------------------------
__global__ void conv1x1_relu_kernel(const float* __restrict__ last,
                                    const float* __restrict__ w,
                                    const float* __restrict__ bias,
                                    float* __restrict__ out)
{
    int idx = blockIdx.x * 256 + threadIdx.x;   // B*OUTC*HWSZ = 524288
    int px = idx & 1023;
    int o  = (idx >> 10) & 63;
    int b  = idx >> 16;
    const float* lp = last + (size_t)b * 2 * HID * HWSZ + px;
    const float* wp = w + o * 2 * HID;
    float s = bias[o];
#pragma unroll 8
    for (int cc = 0; cc < 2 * HID; cc++)
        s += lp[(size_t)cc * HWSZ] * wp[cc];
    out[idx] = fmaxf(s, 0.f);
}

// ---------------- host orchestration ----------------------------------------
extern "C" void kernel_launch(void* const* d_in, const int* in_sizes, int n_in,
                              void* d_out, int out_size)
{
    const float* features = (const float*)d_in[0];
    const float* w_ih0f = (const float*)d_in[1];
    const float* w_hh0f = (const float*)d_in[2];
    const float* b_ih0f = (const float*)d_in[3];
    const float* b_hh0f = (const float*)d_in[4];
    const float* w_ih0r = (const float*)d_in[5];
    const float* w_hh0r = (const float*)d_in[6];
    const float* b_ih0r = (const float*)d_in[7];
    const float* b_hh0r = (const float*)d_in[8];
    const float* w_ih1f = (const float*)d_in[9];
    const float* w_hh1f = (const float*)d_in[10];
    const float* b_ih1f = (const float*)d_in[11];
    const float* b_hh1f = (const float*)d_in[12];
    const float* w_ih1r = (const float*)d_in[13];
    const float* w_hh1r = (const float*)d_in[14];
    const float* b_ih1r = (const float*)d_in[15];
    const float* b_hh1r = (const float*)d_in[16];
    const float* w_out  = (const float*)d_in[17];
    const float* b_out  = (const float*)d_in[18];
    float* out = (float*)d_out;

    float *gates, *xs1, *h, *c, *last;
    cudaGetSymbolAddress((void**)&gates, g_gates);
    cudaGetSymbolAddress((void**)&xs1,   g_xs1);
    cudaGetSymbolAddress((void**)&h,     g_h);
    cudaGetSymbolAddress((void**)&c,     g_c);
    cudaGetSymbolAddress((void**)&last,  g_last);

    dim3 blk(128);
    const int cell2 = (2 * BB * HID * HWSZ) / 256;   // both dirs
    const int cell1 = (BB * HID * HWSZ) / 256;       // one dir

    // ===== Layer 0: ih gates for all (dir, t) in one launch (biases folded) =====
    conv3x3_kernel<CINC, 0><<<dim3(2, 8, 2 * TT * BB), blk>>>(
        features, w_ih0f, w_ih0r, b_ih0f, b_hh0f, b_ih0r, b_hh0r, gates, 0);

    // t = 0: h=c=0 so conv_hh contributes nothing (biases already folded)
    cell_kernel<<<cell2, 256>>>(gates, h, c, xs1, nullptr, 0, 1, 0, 2);
    for (int t = 1; t < TT; t++) {
        conv3x3_kernel<HID, 1><<<dim3(2, 8, 2 * BB), blk>>>(
            h, w_hh0f, w_hh0r, nullptr, nullptr, nullptr, nullptr, gates, t);
        cell_kernel<<<cell2, 256>>>(gates, h, c, xs1, nullptr, t, 0, 0, 2);
    }

    // ===== Layer 1 reverse: only hr1[T-1] is needed (single step, h0=0) =====
    float* gates_rev = gates + (size_t)TT * BB * GG * HWSZ;
    conv3x3_kernel<CINC, 2><<<dim3(2, 8, BB), blk>>>(
        xs1 + (size_t)(TT - 1) * BB * 2 * HID * HWSZ,
        w_ih1r, nullptr, b_ih1r, b_hh1r, nullptr, nullptr, gates_rev, 0);
    cell_kernel<<<cell1, 256>>>(gates_rev,
                                h + (size_t)BB * HID * HWSZ,   // scratch region
                                c + (size_t)BB * HID * HWSZ,
                                nullptr, last, 0, 1, HID, 1);

    // ===== Layer 1 forward =====
    conv3x3_kernel<CINC, 2><<<dim3(2, 8, TT * BB), blk>>>(
        xs1, w_ih1f, nullptr, b_ih1f, b_hh1f, nullptr, nullptr, gates, 0);
    cell_kernel<<<cell1, 256>>>(gates, h, c, nullptr, nullptr, 0, 1, 0, 1);
    for (int t = 1; t < TT; t++) {
        conv3x3_kernel<HID, 1><<<dim3(2, 8, BB), blk>>>(
            h, w_hh1f, nullptr, nullptr, nullptr, nullptr, nullptr, gates, t);
        cell_kernel<<<cell1, 256>>>(gates, h, c, nullptr,
                                    (t == TT - 1) ? last : nullptr, t, 0, 0, 1);
    }

    // ===== 1x1 conv + ReLU =====
    conv1x1_relu_kernel<<<(BB * OUTC * HWSZ) / 256, 256>>>(last, w_out, b_out, out);
}